// round 15
// baseline (speedup 1.0000x reference)
#include <cuda_runtime.h>
#include <cuda_bf16.h>
#include <cuda_fp16.h>
#include <cstdint>

#define BB 8
#define NN 4096
#define KK 20
#define CC 64
#define MM (BB*NN)
#define PPB (NN*KK)
#define CNT (NN*KK)
#define PTS (MM*KK)
#define EPSN 1e-5f
#define SLOPE 0.01f
#define SWZ(kb) ((kb) ^ ((kb)<<1))   // {0,3,6,5}

__device__ __half d_Ph[MM*CC];
__device__ __half d_Uh[MM*CC];
__device__ uint4 d_h2q[(size_t)PTS*8];      // fp16x8 per uint4, key ((blk*4+ngp)*8+mtg)*32+lane
__device__ unsigned d_h3maxu[MM*CC];
__device__ float d_stats[6*BB*CC];
__device__ uint4 d_Bf2[1024];               // precomputed B fragments (W2): [0,512)=HI, [512,1024)=LO
__device__ uint4 d_Bf3[1024];               // same for W3
__device__ int   d_is64;

__device__ __forceinline__ float leaky(float v){ return fmaxf(v, SLOPE*v); }
__device__ __forceinline__ int load_ind(const void* ind, int p, int is64){
    if (is64) return (int)((const long long*)ind)[p];
    return ((const int*)ind)[p];
}
__device__ __forceinline__ unsigned long long ffma2(unsigned long long a,
                                                    unsigned long long b,
                                                    unsigned long long c){
    unsigned long long d;
    asm("fma.rn.f32x2 %0, %1, %2, %3;" : "=l"(d) : "l"(a), "l"(b), "l"(c));
    return d;
}
__device__ __forceinline__ unsigned long long dup2(float v){
    unsigned long long d; asm("mov.b64 %0, {%1, %1};" : "=l"(d) : "f"(v)); return d;
}
__device__ __forceinline__ void unpack2(unsigned long long p, float& lo, float& hi){
    asm("mov.b64 {%0, %1}, %2;" : "=f"(lo), "=f"(hi) : "l"(p));
}
__device__ __forceinline__ unsigned fkey(float v){
    unsigned u = __float_as_uint(v);
    return u ^ ((u & 0x80000000u) ? 0xFFFFFFFFu : 0x80000000u);
}
__device__ __forceinline__ float fkey_inv(unsigned k){
    unsigned u = (k & 0x80000000u) ? (k ^ 0x80000000u) : ~k;
    return __uint_as_float(u);
}
__device__ __forceinline__ float2 h2f2(uint32_t u){
    __half2 h = *(__half2*)&u; return __half22float2(h);
}
__device__ __forceinline__ uint32_t f2h2(float a, float b){
    __half2 h = __floats2half2_rn(a, b); return *(uint32_t*)&h;
}
// m16n8k16 bf16 mma, fp32 accum. C: c0=[r][2q] c1=[r][2q+1] c2=[r+8][2q] c3=[r+8][2q+1]
__device__ __forceinline__ void mma16(float* c, const uint32_t* a, uint32_t b0, uint32_t b1){
    asm volatile("mma.sync.aligned.m16n8k16.row.col.f32.bf16.bf16.f32 "
        "{%0,%1,%2,%3}, {%4,%5,%6,%7}, {%8,%9}, {%0,%1,%2,%3};"
        : "+f"(c[0]),"+f"(c[1]),"+f"(c[2]),"+f"(c[3])
        : "r"(a[0]),"r"(a[1]),"r"(a[2]),"r"(a[3]), "r"(b0),"r"(b1));
}
__device__ __forceinline__ void bfsplit2(float x0, float x1, uint32_t& hi, uint32_t& lo){
    __nv_bfloat162 h = __floats2bfloat162_rn(x0, x1);
    float f0 = __bfloat162float(h.x), f1 = __bfloat162float(h.y);
    __nv_bfloat162 l = __floats2bfloat162_rn(x0 - f0, x1 - f1);
    hi = *(uint32_t*)&h; lo = *(uint32_t*)&l;
}

// ---- shared layout (u32 offsets) ----
#define SA_HI  0       // A frags hi: [4 kb][8 mtg][32 slot][4 u32]
#define SA_LO  4096
#define SB_HI  8192    // B frags hi: [4 kb][4 ntp][32 lane][4 u32]
#define SB_LO  10240   // == SB_HI + 2048 (contiguous with SB_HI)
#define S_MEAN 12288
#define S_RSTD 12352
#define S_SSUM 12416
#define S_SSQ  12480
#define S_IND  12544
#define S_END  12672   // 50688 B; MODE3 staging (128x68 floats) reuses [0, 8704)

// ---------------- small kernels ----------------
__global__ void k_init(const int* ind32){
    int t = blockIdx.x*blockDim.x + threadIdx.x;
    if (t < 6*BB*CC) d_stats[t] = 0.f;
    if (t < MM*CC) d_h3maxu[t] = 0u;
    if (t == 0){
        int is64 = 1;
        for (int i = 0; i < 128; i++) if (ind32[2*i+1] != 0){ is64 = 0; break; }
        d_is64 = is64;
    }
}

// ---------------- KW: precompute B fragment images for W2 / W3 ----------------
__global__ void kw(const float* __restrict__ W2, const float* __restrict__ W3){
    const float* W = (blockIdx.x == 0) ? W2 : W3;
    uint4* dst = (blockIdx.x == 0) ? d_Bf2 : d_Bf3;
    int item = threadIdx.x;                // 512 items
    int kb = item>>7, ntp = (item>>5)&3, ln = item&31;
    int rr = ln>>2, qq = ln&3;
    int n0 = ntp*16 + rr, n1 = n0 + 8;
    int k0 = kb*16 + 2*qq;
    uint32_t h00,l00,h01,l01,h10,l10,h11,l11;
    bfsplit2(W[n0*64+k0],   W[n0*64+k0+1], h00, l00);
    bfsplit2(W[n0*64+k0+8], W[n0*64+k0+9], h01, l01);
    bfsplit2(W[n1*64+k0],   W[n1*64+k0+1], h10, l10);
    bfsplit2(W[n1*64+k0+8], W[n1*64+k0+9], h11, l11);
    dst[item]       = make_uint4(h00,h01,h10,h11);
    dst[item + 512] = make_uint4(l00,l01,l10,l11);
}

// ---------------- K0: P = x@W1a^T, U = x@(W1b-W1a)^T (FFMA2, fp16 out) ----------------
__global__ void __launch_bounds__(256) k0(const float* __restrict__ x,
                                          const float* __restrict__ W1){
    extern __shared__ float sm[];
    float* xT = sm; float* Wa = sm + 64*68; float* Wd = Wa + 4096;
    int tid = threadIdx.y*16 + threadIdx.x;
    int m0 = blockIdx.x*64;
    for (int i = tid; i < 4096; i += 256){
        int c = i>>6, d = i&63;
        float a = W1[c*128+d], b = W1[c*128+64+d];
        Wa[d*64+c] = a; Wd[d*64+c] = b - a;
    }
    for (int i = tid; i < 1024; i += 256){
        int r = i>>4, c4 = i&15;
        float4 v = *(const float4*)(x + (m0+r)*64 + c4*4);
        xT[(c4*4+0)*68+r]=v.x; xT[(c4*4+1)*68+r]=v.y;
        xT[(c4*4+2)*68+r]=v.z; xT[(c4*4+3)*68+r]=v.w;
    }
    __syncthreads();
    int c0 = threadIdx.x*4, r0 = threadIdx.y*4;
    unsigned long long aP[4][2], aU[4][2];
    #pragma unroll
    for (int i=0;i<4;i++){ aP[i][0]=aP[i][1]=aU[i][0]=aU[i][1]=0ULL; }
    for (int d = 0; d < 64; d++){
        float4 xv = *(const float4*)(xT + d*68 + r0);
        ulonglong2 wa = *(const ulonglong2*)(Wa + d*64 + c0);
        ulonglong2 wd = *(const ulonglong2*)(Wd + d*64 + c0);
        float xs[4] = {xv.x,xv.y,xv.z,xv.w};
        #pragma unroll
        for (int i=0;i<4;i++){
            unsigned long long xd = dup2(xs[i]);
            aP[i][0]=ffma2(xd,wa.x,aP[i][0]); aP[i][1]=ffma2(xd,wa.y,aP[i][1]);
            aU[i][0]=ffma2(xd,wd.x,aU[i][0]); aU[i][1]=ffma2(xd,wd.y,aU[i][1]);
        }
    }
    #pragma unroll
    for (int i=0;i<4;i++){
        int row = (m0+r0+i)*64 + c0;
        float p0,p1,p2,p3,u0,u1,u2,u3;
        unpack2(aP[i][0],p0,p1); unpack2(aP[i][1],p2,p3);
        unpack2(aU[i][0],u0,u1); unpack2(aU[i][1],u2,u3);
        *(uint2*)(d_Ph + row) = make_uint2(f2h2(p0,p1), f2h2(p2,p3));
        *(uint2*)(d_Uh + row) = make_uint2(f2h2(u0,u1), f2h2(u2,u3));
    }
}

// ---------------- K1: stage-1 stats (uint4 gather, shfl-reduced) ----------------
__global__ void __launch_bounds__(256) k1(const void* __restrict__ ind_){
    __shared__ float ssum[64], ssq[64];
    int tid = threadIdx.x, blk = blockIdx.x, b = blk>>7;
    int is64 = d_is64;
    int c8 = tid&7, slot = tid>>3;       // 32 point-slots, 8 lanes/point
    int pbase = blk*640;
    float s[8], s2[8];
    #pragma unroll
    for (int j=0;j<8;j++){ s[j]=0.f; s2[j]=0.f; }
    for (int it = 0; it < 20; it++){
        int gp = pbase + it*32 + slot;
        int idx = load_ind(ind_, gp, is64);
        int m = gp / KK;
        uint4 pv = *(const uint4*)(d_Ph + idx*64 + c8*8);
        uint4 uv = *(const uint4*)(d_Uh + m*64 + c8*8);
        uint32_t pu[4] = {pv.x,pv.y,pv.z,pv.w};
        uint32_t uu[4] = {uv.x,uv.y,uv.z,uv.w};
        #pragma unroll
        for (int k=0;k<4;k++){
            float2 a = h2f2(pu[k]), c = h2f2(uu[k]);
            float h0 = a.x + c.x, h1 = a.y + c.y;
            s[2*k] += h0; s2[2*k] += h0*h0;
            s[2*k+1] += h1; s2[2*k+1] += h1*h1;
        }
    }
    #pragma unroll
    for (int j=0;j<8;j++){
        s[j]  += __shfl_xor_sync(0xffffffffu, s[j], 8);
        s2[j] += __shfl_xor_sync(0xffffffffu, s2[j], 8);
        s[j]  += __shfl_xor_sync(0xffffffffu, s[j], 16);
        s2[j] += __shfl_xor_sync(0xffffffffu, s2[j], 16);
    }
    if (tid < 64){ ssum[tid]=0.f; ssq[tid]=0.f; }
    __syncthreads();
    if ((tid&31) < 8){
        #pragma unroll
        for (int j=0;j<8;j++){
            atomicAdd(&ssum[c8*8+j], s[j]);
            atomicAdd(&ssq [c8*8+j], s2[j]);
        }
    }
    __syncthreads();
    if (tid < 64){
        atomicAdd(&d_stats[0*512 + b*64 + tid], ssum[tid]);
        atomicAdd(&d_stats[1*512 + b*64 + tid], ssq[tid]);
    }
}

// ---------------- kmma<MODE>: one GEMM stage, warp = 2 mtiles x 4 ntiles ----------------
template<int MODE>
__global__ void __launch_bounds__(256,3) kmma(const void* __restrict__ ind_){
    extern __shared__ float sm[];
    uint32_t* smu = (uint32_t*)sm;
    int* smi = (int*)sm;
    int tid = threadIdx.x;
    int w = tid>>5, lane = tid&31, r = lane>>2, q = lane&3;
    int wq = w>>2, wm = w&3;               // channel-half, row-quarter
    int blk = blockIdx.x;
    int P0 = blk*128;
    int b = P0 / PPB;

    if (tid < 64){
        int si = (MODE==2?0:2)*512;
        float s  = d_stats[si + b*64 + tid];
        float s2 = d_stats[si + 512 + b*64 + tid];
        float mu = s*(1.f/(float)CNT);
        float var = s2*(1.f/(float)CNT) - mu*mu;
        sm[S_MEAN+tid] = mu; sm[S_RSTD+tid] = rsqrtf(var+EPSN);
        sm[S_SSUM+tid] = 0.f; sm[S_SSQ+tid] = 0.f;
    }
    if (MODE == 2 && tid < 128) smi[S_IND + tid] = load_ind(ind_, P0 + tid, d_is64);

    // B fragments: copy precomputed images (HI then LO, contiguous region)
    {
        const uint4* Bf = (MODE==2) ? d_Bf2 : d_Bf3;
        #pragma unroll
        for (int i=0;i<4;i++){
            int item = i*256 + tid;          // 1024 items (512 hi + 512 lo)
            *(uint4*)&smu[SB_HI + item*4] = Bf[item];
        }
    }
    __syncthreads();

    // A fragments (bf16 hi/lo), slot lt = (rr*4+pl)^SWZ(kb)
    if (MODE == 2){
        #pragma unroll
        for (int i=0;i<4;i++){
            int item = i*256 + tid;          // 1024 items = 64 rowpairs x 16 c4
            int c4 = item & 15, pr = item >> 4;
            int rr = pr & 7, wp = pr >> 3;   // wp = mtg
            int p0 = wp*16 + rr, p1 = p0 + 8;
            int idx0 = smi[S_IND+p0], idx1 = smi[S_IND+p1];
            int mA = (P0+p0)/KK, mB = (P0+p1)/KK;
            uint2 pv0 = *(const uint2*)(d_Ph + idx0*64 + c4*4);
            uint2 uv0 = *(const uint2*)(d_Uh + mA*64 + c4*4);
            uint2 pv1 = *(const uint2*)(d_Ph + idx1*64 + c4*4);
            uint2 uv1 = *(const uint2*)(d_Uh + mB*64 + c4*4);
            float2 pa0 = h2f2(pv0.x), pb0 = h2f2(pv0.y);
            float2 ua0 = h2f2(uv0.x), ub0 = h2f2(uv0.y);
            float2 pa1 = h2f2(pv1.x), pb1 = h2f2(pv1.y);
            float2 ua1 = h2f2(uv1.x), ub1 = h2f2(uv1.y);
            float h0[4] = {pa0.x+ua0.x, pa0.y+ua0.y, pb0.x+ub0.x, pb0.y+ub0.y};
            float h1[4] = {pa1.x+ua1.x, pa1.y+ua1.y, pb1.x+ub1.x, pb1.y+ub1.y};
            float g0[4], g1[4];
            #pragma unroll
            for (int j=0;j<4;j++){
                int c = c4*4+j;
                float mu = sm[S_MEAN+c], rs = sm[S_RSTD+c];
                g0[j] = leaky((h0[j]-mu)*rs);
                g1[j] = leaky((h1[j]-mu)*rs);
            }
            int kb = c4>>2, jj = c4&3, pih = jj>>1;
            #pragma unroll
            for (int e=0;e<2;e++){
                uint32_t ha,la,hb,lb;
                bfsplit2(g0[2*e], g0[2*e+1], ha, la);
                bfsplit2(g1[2*e], g1[2*e+1], hb, lb);
                int pl = 2*(jj&1) + e;
                int lt = (rr*4 + pl)^SWZ(kb);
                int o = ((kb*8 + wp)*32 + lt)*4 + 2*pih;
                *(uint2*)&smu[SA_HI + o] = make_uint2(ha, hb);
                *(uint2*)&smu[SA_LO + o] = make_uint2(la, lb);
            }
        }
    } else {
        // read h2q (uint4 = ntg pair = both pih halves of slot kb=ngp); one STS.128 per hi/lo
        #pragma unroll
        for (int ngp=0;ngp<4;ngp++){
            uint4 u = d_h2q[((size_t)(blk*4+ngp)*8 + w)*32 + lane];
            uint32_t us[4] = {u.x, u.y, u.z, u.w};
            uint32_t hi[4], lo[4];
            #pragma unroll
            for (int s=0;s<2;s++){
                int nt = 2*ngp + s;
                float2 v01 = h2f2(us[2*s]);      // rows r:   (c0, c0+1)
                float2 v23 = h2f2(us[2*s+1]);    // rows r+8: (c0, c0+1)
                int c0 = nt*8 + 2*q;
                float m0 = sm[S_MEAN+c0],   r0v = sm[S_RSTD+c0];
                float m1 = sm[S_MEAN+c0+1], r1v = sm[S_RSTD+c0+1];
                float g0 = leaky((v01.x-m0)*r0v), g1 = leaky((v01.y-m1)*r1v);
                float g2 = leaky((v23.x-m0)*r0v), g3 = leaky((v23.y-m1)*r1v);
                bfsplit2(g0, g1, hi[2*s],   lo[2*s]);
                bfsplit2(g2, g3, hi[2*s+1], lo[2*s+1]);
            }
            int lt = (r*4 + q)^SWZ(ngp);
            int o = ((ngp*8 + w)*32 + lt)*4;
            *(uint4*)&smu[SA_HI + o] = make_uint4(hi[0],hi[1],hi[2],hi[3]);
            *(uint4*)&smu[SA_LO + o] = make_uint4(lo[0],lo[1],lo[2],lo[3]);
        }
    }
    __syncthreads();

    // ---- mainloop: warp owns mtiles {wm*2, wm*2+1}, ntiles {wq*4..+3} ----
    float acc[2][4][4];
    #pragma unroll
    for (int mt=0;mt<2;mt++)
        #pragma unroll
        for (int nt=0;nt<4;nt++)
            #pragma unroll
            for (int e=0;e<4;e++) acc[mt][nt][e] = 0.f;

    int mtg0 = wm*2, mtg1 = mtg0+1;
    #pragma unroll
    for (int kb=0;kb<4;kb++){
        int sl = (lane^SWZ(kb))*4;
        uint4 ah0v = *(uint4*)&smu[SA_HI + (kb*8+mtg0)*128 + sl];
        uint4 al0v = *(uint4*)&smu[SA_LO + (kb*8+mtg0)*128 + sl];
        uint4 ah1v = *(uint4*)&smu[SA_HI + (kb*8+mtg1)*128 + sl];
        uint4 al1v = *(uint4*)&smu[SA_LO + (kb*8+mtg1)*128 + sl];
        uint32_t ah0[4] = {ah0v.x,ah0v.y,ah0v.z,ah0v.w};
        uint32_t al0[4] = {al0v.x,al0v.y,al0v.z,al0v.w};
        uint32_t ah1[4] = {ah1v.x,ah1v.y,ah1v.z,ah1v.w};
        uint32_t al1[4] = {al1v.x,al1v.y,al1v.z,al1v.w};
        int bo0 = (kb*4 + wq*2)*128 + lane*4;
        uint4 bh0 = *(uint4*)&smu[SB_HI + bo0];
        uint4 bh1 = *(uint4*)&smu[SB_HI + bo0 + 128];
        uint4 bl0 = *(uint4*)&smu[SB_LO + bo0];
        uint4 bl1 = *(uint4*)&smu[SB_LO + bo0 + 128];
        // hi*hi
        mma16(acc[0][0], ah0, bh0.x, bh0.y); mma16(acc[0][1], ah0, bh0.z, bh0.w);
        mma16(acc[0][2], ah0, bh1.x, bh1.y); mma16(acc[0][3], ah0, bh1.z, bh1.w);
        mma16(acc[1][0], ah1, bh0.x, bh0.y); mma16(acc[1][1], ah1, bh0.z, bh0.w);
        mma16(acc[1][2], ah1, bh1.x, bh1.y); mma16(acc[1][3], ah1, bh1.z, bh1.w);
        // hi*lo
        mma16(acc[0][0], ah0, bl0.x, bl0.y); mma16(acc[0][1], ah0, bl0.z, bl0.w);
        mma16(acc[0][2], ah0, bl1.x, bl1.y); mma16(acc[0][3], ah0, bl1.z, bl1.w);
        mma16(acc[1][0], ah1, bl0.x, bl0.y); mma16(acc[1][1], ah1, bl0.z, bl0.w);
        mma16(acc[1][2], ah1, bl1.x, bl1.y); mma16(acc[1][3], ah1, bl1.z, bl1.w);
        // lo*hi
        mma16(acc[0][0], al0, bh0.x, bh0.y); mma16(acc[0][1], al0, bh0.z, bh0.w);
        mma16(acc[0][2], al0, bh1.x, bh1.y); mma16(acc[0][3], al0, bh1.z, bh1.w);
        mma16(acc[1][0], al1, bh0.x, bh0.y); mma16(acc[1][1], al1, bh0.z, bh0.w);
        mma16(acc[1][2], al1, bh1.x, bh1.y); mma16(acc[1][3], al1, bh1.z, bh1.w);
    }

    // ---- stats: channels c = (wq*4+nt)*8 + 2q + e, reduce rows via shfl over r ----
    int so = (MODE==2?2:4)*512;
    #pragma unroll
    for (int nt=0;nt<4;nt++){
        #pragma unroll
        for (int e=0;e<2;e++){
            float v0 = acc[0][nt][e], v1 = acc[0][nt][e+2];
            float v2 = acc[1][nt][e], v3 = acc[1][nt][e+2];
            float s  = v0+v1+v2+v3;
            float s2 = v0*v0+v1*v1+v2*v2+v3*v3;
            s  += __shfl_xor_sync(0xffffffffu, s, 16);
            s2 += __shfl_xor_sync(0xffffffffu, s2, 16);
            s  += __shfl_xor_sync(0xffffffffu, s, 8);
            s2 += __shfl_xor_sync(0xffffffffu, s2, 8);
            s  += __shfl_xor_sync(0xffffffffu, s, 4);
            s2 += __shfl_xor_sync(0xffffffffu, s2, 4);
            if (r == 0){
                int c = (wq*4+nt)*8 + 2*q + e;
                atomicAdd(&sm[S_SSUM+c], s);
                atomicAdd(&sm[S_SSQ+c], s2);
            }
        }
    }

    if (MODE == 2){
        // h2 store: uint4 per (mtg, ngp) — fp16x8, coalesced 512B/warp
        #pragma unroll
        for (int mt=0;mt<2;mt++){
            int mtg = wm*2+mt;
            #pragma unroll
            for (int np=0;np<2;np++){
                int ngp = wq*2+np;
                uint4 u = make_uint4(
                    f2h2(acc[mt][2*np][0],   acc[mt][2*np][1]),
                    f2h2(acc[mt][2*np][2],   acc[mt][2*np][3]),
                    f2h2(acc[mt][2*np+1][0], acc[mt][2*np+1][1]),
                    f2h2(acc[mt][2*np+1][2], acc[mt][2*np+1][3]));
                d_h2q[((size_t)(blk*4+ngp)*8 + mtg)*32 + lane] = u;
            }
        }
        __syncthreads();
        if (tid < 64){
            atomicAdd(&d_stats[so + b*64 + tid], sm[S_SSUM+tid]);
            atomicAdd(&d_stats[so + 512 + b*64 + tid], sm[S_SSQ+tid]);
        }
    } else {
        __syncthreads();   // frag regions dead; reuse [0, 8704) as row-major h3
        #pragma unroll
        for (int mt=0;mt<2;mt++)
            #pragma unroll
            for (int nt=0;nt<4;nt++){
                int cb = (wq*4+nt)*8 + 2*q;
                int pb = (wm*2+mt)*16 + r;
                sm[pb*68 + cb]       = acc[mt][nt][0];
                sm[pb*68 + cb+1]     = acc[mt][nt][1];
                sm[(pb+8)*68 + cb]   = acc[mt][nt][2];
                sm[(pb+8)*68 + cb+1] = acc[mt][nt][3];
            }
        __syncthreads();
        if (tid < 64){
            atomicAdd(&d_stats[so + b*64 + tid], sm[S_SSUM+tid]);
            atomicAdd(&d_stats[so + 512 + b*64 + tid], sm[S_SSQ+tid]);
        }
        int g0 = P0/KK;
        for (int item = tid; item < 512; item += 256){
            int g = g0 + (item>>6), c = item&63;
            int lo2 = g*KK - P0, hi2 = lo2 + KK;
            lo2 = max(lo2, 0); hi2 = min(hi2, 128);
            if (lo2 < hi2 && g < MM){
                float mx = sm[lo2*68 + c];
                for (int p = lo2+1; p < hi2; p++) mx = fmaxf(mx, sm[p*68 + c]);
                atomicMax(&d_h3maxu[g*64 + c], fkey(mx));
            }
        }
    }
}

// ---------------- K4: norm3 + leaky on maxed h3 -> out ----------------
__global__ void __launch_bounds__(256) k4(float* __restrict__ out){
    int g = blockIdx.x*256 + threadIdx.x;
    int c = g & 63;
    int b = g >> 18;
    float s  = d_stats[4*512 + b*64 + c];
    float s2 = d_stats[5*512 + b*64 + c];
    float mu = s*(1.f/(float)CNT);
    float var = s2*(1.f/(float)CNT) - mu*mu;
    float r = rsqrtf(var + EPSN);
    out[g] = leaky((fkey_inv(d_h3maxu[g]) - mu)*r);
}

// ---------------- launch ----------------
extern "C" void kernel_launch(void* const* d_in, const int* in_sizes, int n_in,
                              void* d_out, int out_size){
    const float* x   = (const float*)d_in[0];
    const void*  ind = d_in[1];
    const float* W1  = (const float*)d_in[2];
    const float* W2  = (const float*)d_in[3];
    const float* W3  = (const float*)d_in[4];

    cudaFuncSetAttribute(k0, cudaFuncAttributeMaxDynamicSharedMemorySize, 50176);
    cudaFuncSetAttribute(kmma<2>, cudaFuncAttributeMaxDynamicSharedMemorySize, S_END*4);
    cudaFuncSetAttribute(kmma<3>, cudaFuncAttributeMaxDynamicSharedMemorySize, S_END*4);

    k_init  <<<8192, 256>>>((const int*)ind);
    kw      <<<2, 512>>>(W2, W3);
    k0      <<<512, dim3(16,16), 50176>>>(x, W1);
    k1      <<<1024, 256>>>(ind);
    kmma<2> <<<5120, 256, S_END*4>>>(ind);
    kmma<3> <<<5120, 256, S_END*4>>>(nullptr);
    k4      <<<8192, 256>>>((float*)d_out);

    (void)in_sizes; (void)n_in; (void)out_size;
}

// round 17
// speedup vs baseline: 1.3771x; 1.3771x over previous
#include <cuda_runtime.h>
#include <cuda_bf16.h>
#include <cuda_fp16.h>
#include <cstdint>

#define BB 8
#define NN 4096
#define KK 20
#define CC 64
#define MM (BB*NN)
#define PPB (NN*KK)
#define CNT (NN*KK)
#define PTS (MM*KK)
#define EPSN 1e-5f
#define SLOPE 0.01f
#define SWZ(kb) ((kb) ^ ((kb)<<1))   // {0,3,6,5}

__device__ __half d_Ph[MM*CC];
__device__ __half d_Uh[MM*CC];
__device__ uint4 d_h2q[(size_t)PTS*8];      // fp16x8 per uint4, key ((blk*4+ngp)*8+mtg)*32+lane
__device__ unsigned d_h3maxu[MM*CC];
__device__ float d_stats[6*BB*CC];
__device__ int   d_is64;

__device__ __forceinline__ float leaky(float v){ return fmaxf(v, SLOPE*v); }
__device__ __forceinline__ int load_ind(const void* ind, int p, int is64){
    if (is64) return (int)((const long long*)ind)[p];
    return ((const int*)ind)[p];
}
__device__ __forceinline__ unsigned long long ffma2(unsigned long long a,
                                                    unsigned long long b,
                                                    unsigned long long c){
    unsigned long long d;
    asm("fma.rn.f32x2 %0, %1, %2, %3;" : "=l"(d) : "l"(a), "l"(b), "l"(c));
    return d;
}
__device__ __forceinline__ unsigned long long dup2(float v){
    unsigned long long d; asm("mov.b64 %0, {%1, %1};" : "=l"(d) : "f"(v)); return d;
}
__device__ __forceinline__ void unpack2(unsigned long long p, float& lo, float& hi){
    asm("mov.b64 {%0, %1}, %2;" : "=f"(lo), "=f"(hi) : "l"(p));
}
__device__ __forceinline__ unsigned fkey(float v){
    unsigned u = __float_as_uint(v);
    return u ^ ((u & 0x80000000u) ? 0xFFFFFFFFu : 0x80000000u);
}
__device__ __forceinline__ float fkey_inv(unsigned k){
    unsigned u = (k & 0x80000000u) ? (k ^ 0x80000000u) : ~k;
    return __uint_as_float(u);
}
__device__ __forceinline__ float2 h2f2(uint32_t u){
    __half2 h = *(__half2*)&u; return __half22float2(h);
}
__device__ __forceinline__ uint32_t f2h2(float a, float b){
    __half2 h = __floats2half2_rn(a, b); return *(uint32_t*)&h;
}
// m16n8k16 bf16 mma, fp32 accum. C: c0=[r][2q] c1=[r][2q+1] c2=[r+8][2q] c3=[r+8][2q+1]
__device__ __forceinline__ void mma16(float* c, const uint32_t* a, uint32_t b0, uint32_t b1){
    asm volatile("mma.sync.aligned.m16n8k16.row.col.f32.bf16.bf16.f32 "
        "{%0,%1,%2,%3}, {%4,%5,%6,%7}, {%8,%9}, {%0,%1,%2,%3};"
        : "+f"(c[0]),"+f"(c[1]),"+f"(c[2]),"+f"(c[3])
        : "r"(a[0]),"r"(a[1]),"r"(a[2]),"r"(a[3]), "r"(b0),"r"(b1));
}
__device__ __forceinline__ void bfsplit2(float x0, float x1, uint32_t& hi, uint32_t& lo){
    __nv_bfloat162 h = __floats2bfloat162_rn(x0, x1);
    float f0 = __bfloat162float(h.x), f1 = __bfloat162float(h.y);
    __nv_bfloat162 l = __floats2bfloat162_rn(x0 - f0, x1 - f1);
    hi = *(uint32_t*)&h; lo = *(uint32_t*)&l;
}

// ---- shared layout (u32 offsets) ----
#define SA_HI  0       // A frags hi: [4 kb][8 mtg][32 slot][4 u32]
#define SA_LO  4096
#define SB_HI  8192    // B frags hi: [4 kb][4 ntp][32 lane][4 u32]
#define SB_LO  10240
#define S_MEAN 12288
#define S_RSTD 12352
#define S_SSUM 12416
#define S_SSQ  12480
#define S_IND  12544
#define S_END  12672   // 50688 B; MODE3 staging (128x68 floats) reuses [0, 8704)

// ---------------- small kernels ----------------
__global__ void k_init(const int* ind32){
    int t = blockIdx.x*blockDim.x + threadIdx.x;
    if (t < 6*BB*CC) d_stats[t] = 0.f;
    if (t < MM*CC) d_h3maxu[t] = 0u;
    if (t == 0){
        int is64 = 1;
        for (int i = 0; i < 128; i++) if (ind32[2*i+1] != 0){ is64 = 0; break; }
        d_is64 = is64;
    }
}

// ---------------- K0: P = x@W1a^T, U = x@(W1b-W1a)^T (FFMA2, fp16 out) ----------------
__global__ void __launch_bounds__(256) k0(const float* __restrict__ x,
                                          const float* __restrict__ W1){
    extern __shared__ float sm[];
    float* xT = sm; float* Wa = sm + 64*68; float* Wd = Wa + 4096;
    int tid = threadIdx.y*16 + threadIdx.x;
    int m0 = blockIdx.x*64;
    for (int i = tid; i < 4096; i += 256){
        int c = i>>6, d = i&63;
        float a = W1[c*128+d], b = W1[c*128+64+d];
        Wa[d*64+c] = a; Wd[d*64+c] = b - a;
    }
    for (int i = tid; i < 1024; i += 256){
        int r = i>>4, c4 = i&15;
        float4 v = *(const float4*)(x + (m0+r)*64 + c4*4);
        xT[(c4*4+0)*68+r]=v.x; xT[(c4*4+1)*68+r]=v.y;
        xT[(c4*4+2)*68+r]=v.z; xT[(c4*4+3)*68+r]=v.w;
    }
    __syncthreads();
    int c0 = threadIdx.x*4, r0 = threadIdx.y*4;
    unsigned long long aP[4][2], aU[4][2];
    #pragma unroll
    for (int i=0;i<4;i++){ aP[i][0]=aP[i][1]=aU[i][0]=aU[i][1]=0ULL; }
    for (int d = 0; d < 64; d++){
        float4 xv = *(const float4*)(xT + d*68 + r0);
        ulonglong2 wa = *(const ulonglong2*)(Wa + d*64 + c0);
        ulonglong2 wd = *(const ulonglong2*)(Wd + d*64 + c0);
        float xs[4] = {xv.x,xv.y,xv.z,xv.w};
        #pragma unroll
        for (int i=0;i<4;i++){
            unsigned long long xd = dup2(xs[i]);
            aP[i][0]=ffma2(xd,wa.x,aP[i][0]); aP[i][1]=ffma2(xd,wa.y,aP[i][1]);
            aU[i][0]=ffma2(xd,wd.x,aU[i][0]); aU[i][1]=ffma2(xd,wd.y,aU[i][1]);
        }
    }
    #pragma unroll
    for (int i=0;i<4;i++){
        int row = (m0+r0+i)*64 + c0;
        float p0,p1,p2,p3,u0,u1,u2,u3;
        unpack2(aP[i][0],p0,p1); unpack2(aP[i][1],p2,p3);
        unpack2(aU[i][0],u0,u1); unpack2(aU[i][1],u2,u3);
        *(uint2*)(d_Ph + row) = make_uint2(f2h2(p0,p1), f2h2(p2,p3));
        *(uint2*)(d_Uh + row) = make_uint2(f2h2(u0,u1), f2h2(u2,u3));
    }
}

// ---------------- K1: stage-1 stats (round-13 version: fp16 uint2, 16-lane) ----------------
__global__ void __launch_bounds__(256) k1(const void* __restrict__ ind_){
    __shared__ float ssum[64], ssq[64];
    int tid = threadIdx.x, blk = blockIdx.x, b = blk>>7;
    int is64 = d_is64;
    int c4 = tid&15, slot = tid>>4;
    int pbase = blk*640;
    float s[4]={0,0,0,0}, s2[4]={0,0,0,0};
    for (int it = 0; it < 40; it++){
        int gp = pbase + it*16 + slot;
        int idx = load_ind(ind_, gp, is64);
        int m = gp / KK;
        uint2 pv = *(const uint2*)(d_Ph + idx*64 + c4*4);
        uint2 uv = *(const uint2*)(d_Uh + m*64 + c4*4);
        float2 pa = h2f2(pv.x), pb = h2f2(pv.y);
        float2 ua = h2f2(uv.x), ub = h2f2(uv.y);
        float h[4] = {pa.x+ua.x, pa.y+ua.y, pb.x+ub.x, pb.y+ub.y};
        #pragma unroll
        for (int q=0;q<4;q++){ s[q]+=h[q]; s2[q]+=h[q]*h[q]; }
    }
    if (tid < 64){ ssum[tid]=0.f; ssq[tid]=0.f; }
    __syncthreads();
    #pragma unroll
    for (int q=0;q<4;q++){ atomicAdd(&ssum[c4*4+q], s[q]); atomicAdd(&ssq[c4*4+q], s2[q]); }
    __syncthreads();
    if (tid < 64){
        atomicAdd(&d_stats[0*512 + b*64 + tid], ssum[tid]);
        atomicAdd(&d_stats[1*512 + b*64 + tid], ssq[tid]);
    }
}

// ---------------- kmma<MODE>: one GEMM stage, warp = 2 mtiles x 4 ntiles ----------------
template<int MODE>
__global__ void __launch_bounds__(256,3) kmma(const void* __restrict__ ind_,
                                              const float* __restrict__ W){
    extern __shared__ float sm[];
    uint32_t* smu = (uint32_t*)sm;
    int* smi = (int*)sm;
    int tid = threadIdx.x;
    int w = tid>>5, lane = tid&31, r = lane>>2, q = lane&3;
    int wq = w>>2, wm = w&3;               // channel-half, row-quarter
    int blk = blockIdx.x;
    int P0 = blk*128;
    int b = P0 / PPB;

    if (tid < 64){
        int si = (MODE==2?0:2)*512;
        float s  = d_stats[si + b*64 + tid];
        float s2 = d_stats[si + 512 + b*64 + tid];
        float mu = s*(1.f/(float)CNT);
        float var = s2*(1.f/(float)CNT) - mu*mu;
        sm[S_MEAN+tid] = mu; sm[S_RSTD+tid] = rsqrtf(var+EPSN);
        sm[S_SSUM+tid] = 0.f; sm[S_SSQ+tid] = 0.f;
    }
    if (MODE == 2 && tid < 128) smi[S_IND + tid] = load_ind(ind_, P0 + tid, d_is64);

    // B fragments: [kb][ntp][lane][4] = {nt_even.b0,b1, nt_odd.b0,b1}
    #pragma unroll
    for (int i=0;i<2;i++){
        int item = i*256 + tid;
        int kb = item>>7, ntp = (item>>5)&3, ln = item&31;
        int rr = ln>>2, qq = ln&3;
        int n0 = ntp*16 + rr, n1 = n0 + 8;
        int k0 = kb*16 + 2*qq;
        uint32_t h00,l00,h01,l01,h10,l10,h11,l11;
        bfsplit2(W[n0*64+k0],   W[n0*64+k0+1], h00, l00);
        bfsplit2(W[n0*64+k0+8], W[n0*64+k0+9], h01, l01);
        bfsplit2(W[n1*64+k0],   W[n1*64+k0+1], h10, l10);
        bfsplit2(W[n1*64+k0+8], W[n1*64+k0+9], h11, l11);
        *(uint4*)&smu[SB_HI + item*4] = make_uint4(h00,h01,h10,h11);
        *(uint4*)&smu[SB_LO + item*4] = make_uint4(l00,l01,l10,l11);
    }
    __syncthreads();

    // A fragments (bf16 hi/lo), slot lt = (rr*4+pl)^SWZ(kb)
    if (MODE == 2){
        #pragma unroll
        for (int i=0;i<4;i++){
            int item = i*256 + tid;          // 1024 items = 64 rowpairs x 16 c4
            int c4 = item & 15, pr = item >> 4;
            int rr = pr & 7, wp = pr >> 3;   // wp = mtg
            int p0 = wp*16 + rr, p1 = p0 + 8;
            int idx0 = smi[S_IND+p0], idx1 = smi[S_IND+p1];
            int mA = (P0+p0)/KK, mB = (P0+p1)/KK;
            uint2 pv0 = *(const uint2*)(d_Ph + idx0*64 + c4*4);
            uint2 uv0 = *(const uint2*)(d_Uh + mA*64 + c4*4);
            uint2 pv1 = *(const uint2*)(d_Ph + idx1*64 + c4*4);
            uint2 uv1 = *(const uint2*)(d_Uh + mB*64 + c4*4);
            float2 pa0 = h2f2(pv0.x), pb0 = h2f2(pv0.y);
            float2 ua0 = h2f2(uv0.x), ub0 = h2f2(uv0.y);
            float2 pa1 = h2f2(pv1.x), pb1 = h2f2(pv1.y);
            float2 ua1 = h2f2(uv1.x), ub1 = h2f2(uv1.y);
            float h0[4] = {pa0.x+ua0.x, pa0.y+ua0.y, pb0.x+ub0.x, pb0.y+ub0.y};
            float h1[4] = {pa1.x+ua1.x, pa1.y+ua1.y, pb1.x+ub1.x, pb1.y+ub1.y};
            float g0[4], g1[4];
            #pragma unroll
            for (int j=0;j<4;j++){
                int c = c4*4+j;
                float mu = sm[S_MEAN+c], rs = sm[S_RSTD+c];
                g0[j] = leaky((h0[j]-mu)*rs);
                g1[j] = leaky((h1[j]-mu)*rs);
            }
            int kb = c4>>2, jj = c4&3, pih = jj>>1;
            #pragma unroll
            for (int e=0;e<2;e++){
                uint32_t ha,la,hb,lb;
                bfsplit2(g0[2*e], g0[2*e+1], ha, la);
                bfsplit2(g1[2*e], g1[2*e+1], hb, lb);
                int pl = 2*(jj&1) + e;
                int lt = (rr*4 + pl)^SWZ(kb);
                int o = ((kb*8 + wp)*32 + lt)*4 + 2*pih;
                *(uint2*)&smu[SA_HI + o] = make_uint2(ha, hb);
                *(uint2*)&smu[SA_LO + o] = make_uint2(la, lb);
            }
        }
    } else {
        // read h2q (uint4 = ntg pair = both pih halves of slot kb=ngp); one STS.128 per hi/lo
        #pragma unroll
        for (int ngp=0;ngp<4;ngp++){
            uint4 u = d_h2q[((size_t)(blk*4+ngp)*8 + w)*32 + lane];
            uint32_t us[4] = {u.x, u.y, u.z, u.w};
            uint32_t hi[4], lo[4];
            #pragma unroll
            for (int s=0;s<2;s++){
                int nt = 2*ngp + s;
                float2 v01 = h2f2(us[2*s]);      // rows r:   (c0, c0+1)
                float2 v23 = h2f2(us[2*s+1]);    // rows r+8: (c0, c0+1)
                int c0 = nt*8 + 2*q;
                float m0 = sm[S_MEAN+c0],   r0v = sm[S_RSTD+c0];
                float m1 = sm[S_MEAN+c0+1], r1v = sm[S_RSTD+c0+1];
                float g0 = leaky((v01.x-m0)*r0v), g1 = leaky((v01.y-m1)*r1v);
                float g2 = leaky((v23.x-m0)*r0v), g3 = leaky((v23.y-m1)*r1v);
                bfsplit2(g0, g1, hi[2*s],   lo[2*s]);
                bfsplit2(g2, g3, hi[2*s+1], lo[2*s+1]);
            }
            int lt = (r*4 + q)^SWZ(ngp);
            int o = ((ngp*8 + w)*32 + lt)*4;
            *(uint4*)&smu[SA_HI + o] = make_uint4(hi[0],hi[1],hi[2],hi[3]);
            *(uint4*)&smu[SA_LO + o] = make_uint4(lo[0],lo[1],lo[2],lo[3]);
        }
    }
    __syncthreads();

    // ---- mainloop: warp owns mtiles {wm*2, wm*2+1}, ntiles {wq*4..+3} ----
    float acc[2][4][4];
    #pragma unroll
    for (int mt=0;mt<2;mt++)
        #pragma unroll
        for (int nt=0;nt<4;nt++)
            #pragma unroll
            for (int e=0;e<4;e++) acc[mt][nt][e] = 0.f;

    int mtg0 = wm*2, mtg1 = mtg0+1;
    #pragma unroll
    for (int kb=0;kb<4;kb++){
        int sl = (lane^SWZ(kb))*4;
        uint4 ah0v = *(uint4*)&smu[SA_HI + (kb*8+mtg0)*128 + sl];
        uint4 al0v = *(uint4*)&smu[SA_LO + (kb*8+mtg0)*128 + sl];
        uint4 ah1v = *(uint4*)&smu[SA_HI + (kb*8+mtg1)*128 + sl];
        uint4 al1v = *(uint4*)&smu[SA_LO + (kb*8+mtg1)*128 + sl];
        uint32_t ah0[4] = {ah0v.x,ah0v.y,ah0v.z,ah0v.w};
        uint32_t al0[4] = {al0v.x,al0v.y,al0v.z,al0v.w};
        uint32_t ah1[4] = {ah1v.x,ah1v.y,ah1v.z,ah1v.w};
        uint32_t al1[4] = {al1v.x,al1v.y,al1v.z,al1v.w};
        int bo0 = (kb*4 + wq*2)*128 + lane*4;
        uint4 bh0 = *(uint4*)&smu[SB_HI + bo0];
        uint4 bh1 = *(uint4*)&smu[SB_HI + bo0 + 128];
        uint4 bl0 = *(uint4*)&smu[SB_LO + bo0];
        uint4 bl1 = *(uint4*)&smu[SB_LO + bo0 + 128];
        // hi*hi
        mma16(acc[0][0], ah0, bh0.x, bh0.y); mma16(acc[0][1], ah0, bh0.z, bh0.w);
        mma16(acc[0][2], ah0, bh1.x, bh1.y); mma16(acc[0][3], ah0, bh1.z, bh1.w);
        mma16(acc[1][0], ah1, bh0.x, bh0.y); mma16(acc[1][1], ah1, bh0.z, bh0.w);
        mma16(acc[1][2], ah1, bh1.x, bh1.y); mma16(acc[1][3], ah1, bh1.z, bh1.w);
        // hi*lo
        mma16(acc[0][0], ah0, bl0.x, bl0.y); mma16(acc[0][1], ah0, bl0.z, bl0.w);
        mma16(acc[0][2], ah0, bl1.x, bl1.y); mma16(acc[0][3], ah0, bl1.z, bl1.w);
        mma16(acc[1][0], ah1, bl0.x, bl0.y); mma16(acc[1][1], ah1, bl0.z, bl0.w);
        mma16(acc[1][2], ah1, bl1.x, bl1.y); mma16(acc[1][3], ah1, bl1.z, bl1.w);
        // lo*hi
        mma16(acc[0][0], al0, bh0.x, bh0.y); mma16(acc[0][1], al0, bh0.z, bh0.w);
        mma16(acc[0][2], al0, bh1.x, bh1.y); mma16(acc[0][3], al0, bh1.z, bh1.w);
        mma16(acc[1][0], al1, bh0.x, bh0.y); mma16(acc[1][1], al1, bh0.z, bh0.w);
        mma16(acc[1][2], al1, bh1.x, bh1.y); mma16(acc[1][3], al1, bh1.z, bh1.w);
    }

    // ---- stats: channels c = (wq*4+nt)*8 + 2q + e, reduce rows via shfl over r ----
    int so = (MODE==2?2:4)*512;
    #pragma unroll
    for (int nt=0;nt<4;nt++){
        #pragma unroll
        for (int e=0;e<2;e++){
            float v0 = acc[0][nt][e], v1 = acc[0][nt][e+2];
            float v2 = acc[1][nt][e], v3 = acc[1][nt][e+2];
            float s  = v0+v1+v2+v3;
            float s2 = v0*v0+v1*v1+v2*v2+v3*v3;
            s  += __shfl_xor_sync(0xffffffffu, s, 16);
            s2 += __shfl_xor_sync(0xffffffffu, s2, 16);
            s  += __shfl_xor_sync(0xffffffffu, s, 8);
            s2 += __shfl_xor_sync(0xffffffffu, s2, 8);
            s  += __shfl_xor_sync(0xffffffffu, s, 4);
            s2 += __shfl_xor_sync(0xffffffffu, s2, 4);
            if (r == 0){
                int c = (wq*4+nt)*8 + 2*q + e;
                atomicAdd(&sm[S_SSUM+c], s);
                atomicAdd(&sm[S_SSQ+c], s2);
            }
        }
    }

    if (MODE == 2){
        // h2 store: uint4 per (mtg, ngp) — fp16x8, coalesced 512B/warp
        #pragma unroll
        for (int mt=0;mt<2;mt++){
            int mtg = wm*2+mt;
            #pragma unroll
            for (int np=0;np<2;np++){
                int ngp = wq*2+np;
                uint4 u = make_uint4(
                    f2h2(acc[mt][2*np][0],   acc[mt][2*np][1]),
                    f2h2(acc[mt][2*np][2],   acc[mt][2*np][3]),
                    f2h2(acc[mt][2*np+1][0], acc[mt][2*np+1][1]),
                    f2h2(acc[mt][2*np+1][2], acc[mt][2*np+1][3]));
                d_h2q[((size_t)(blk*4+ngp)*8 + mtg)*32 + lane] = u;
            }
        }
        __syncthreads();
        if (tid < 64){
            atomicAdd(&d_stats[so + b*64 + tid], sm[S_SSUM+tid]);
            atomicAdd(&d_stats[so + 512 + b*64 + tid], sm[S_SSQ+tid]);
        }
    } else {
        __syncthreads();   // frag regions dead; reuse [0, 8704) as row-major h3
        #pragma unroll
        for (int mt=0;mt<2;mt++)
            #pragma unroll
            for (int nt=0;nt<4;nt++){
                int cb = (wq*4+nt)*8 + 2*q;
                int pb = (wm*2+mt)*16 + r;
                sm[pb*68 + cb]       = acc[mt][nt][0];
                sm[pb*68 + cb+1]     = acc[mt][nt][1];
                sm[(pb+8)*68 + cb]   = acc[mt][nt][2];
                sm[(pb+8)*68 + cb+1] = acc[mt][nt][3];
            }
        __syncthreads();
        if (tid < 64){
            atomicAdd(&d_stats[so + b*64 + tid], sm[S_SSUM+tid]);
            atomicAdd(&d_stats[so + 512 + b*64 + tid], sm[S_SSQ+tid]);
        }
        int g0 = P0/KK;
        for (int item = tid; item < 512; item += 256){
            int g = g0 + (item>>6), c = item&63;
            int lo2 = g*KK - P0, hi2 = lo2 + KK;
            lo2 = max(lo2, 0); hi2 = min(hi2, 128);
            if (lo2 < hi2 && g < MM){
                float mx = sm[lo2*68 + c];
                for (int p = lo2+1; p < hi2; p++) mx = fmaxf(mx, sm[p*68 + c]);
                atomicMax(&d_h3maxu[g*64 + c], fkey(mx));
            }
        }
    }
}

// ---------------- K4: norm3 + leaky on maxed h3 -> out ----------------
__global__ void __launch_bounds__(256) k4(float* __restrict__ out){
    int g = blockIdx.x*256 + threadIdx.x;
    int c = g & 63;
    int b = g >> 18;
    float s  = d_stats[4*512 + b*64 + c];
    float s2 = d_stats[5*512 + b*64 + c];
    float mu = s*(1.f/(float)CNT);
    float var = s2*(1.f/(float)CNT) - mu*mu;
    float r = rsqrtf(var + EPSN);
    out[g] = leaky((fkey_inv(d_h3maxu[g]) - mu)*r);
}

// ---------------- launch ----------------
extern "C" void kernel_launch(void* const* d_in, const int* in_sizes, int n_in,
                              void* d_out, int out_size){
    const float* x   = (const float*)d_in[0];
    const void*  ind = d_in[1];
    const float* W1  = (const float*)d_in[2];
    const float* W2  = (const float*)d_in[3];
    const float* W3  = (const float*)d_in[4];

    cudaFuncSetAttribute(k0, cudaFuncAttributeMaxDynamicSharedMemorySize, 50176);
    cudaFuncSetAttribute(kmma<2>, cudaFuncAttributeMaxDynamicSharedMemorySize, S_END*4);
    cudaFuncSetAttribute(kmma<3>, cudaFuncAttributeMaxDynamicSharedMemorySize, S_END*4);

    k_init  <<<8192, 256>>>((const int*)ind);
    k0      <<<512, dim3(16,16), 50176>>>(x, W1);
    k1      <<<1024, 256>>>(ind);
    kmma<2> <<<5120, 256, S_END*4>>>(ind, W2);
    kmma<3> <<<5120, 256, S_END*4>>>(nullptr, W3);
    k4      <<<8192, 256>>>((float*)d_out);

    (void)in_sizes; (void)n_in; (void)out_size;
}